// round 2
// baseline (speedup 1.0000x reference)
#include <cuda_runtime.h>
#include <cstdint>

// Problem constants (fixed by the reference)
#define NN      100000
#define IN_DIM  256
#define HID     256
#define EMB     64
#define BN_EPS  1e-3f

// ---------------------------------------------------------------------------
// Scratch (device globals: no runtime allocation allowed)
// ---------------------------------------------------------------------------
__device__ float g_xw1[(size_t)NN * HID];   // x @ w1'  (102.4 MB)
__device__ float g_h  [(size_t)NN * HID];   // spmm1 accumulator == BN1 output (pre-ReLU)
__device__ float g_hw2[(size_t)NN * EMB];   // relu(h) @ w2'  (25.6 MB)
__device__ float g_w1s[IN_DIM * HID];       // w1 with BN1 scale folded into columns
__device__ float g_w2s[HID * EMB];          // w2 with BN2 scale folded into columns
__device__ float g_b1[HID];                 // beta1 - mean1*s1
__device__ float g_b2[EMB];                 // beta2 - mean2*s2

// ---------------------------------------------------------------------------
// Vectorized global reduction (sm_90+): 4x fewer atomic ops than scalar
// ---------------------------------------------------------------------------
__device__ __forceinline__ void red_add_v4(float* addr, float a, float b, float c, float d) {
    asm volatile("red.global.add.v4.f32 [%0], {%1,%2,%3,%4};"
                 :: "l"(addr), "f"(a), "f"(b), "f"(c), "f"(d) : "memory");
}

// ---------------------------------------------------------------------------
// Prep: fold BN scale into weight columns, compute bias vectors
// ---------------------------------------------------------------------------
__global__ void prep_kernel(const float* __restrict__ w1, const float* __restrict__ w2,
                            const float* __restrict__ g1, const float* __restrict__ be1,
                            const float* __restrict__ m1, const float* __restrict__ v1,
                            const float* __restrict__ g2, const float* __restrict__ be2,
                            const float* __restrict__ m2, const float* __restrict__ v2) {
    int j = threadIdx.x;
    if (j < HID) {
        float s = g1[j] * rsqrtf(v1[j] + BN_EPS);
        g_b1[j] = be1[j] - m1[j] * s;
        for (int i = 0; i < IN_DIM; i++)
            g_w1s[i * HID + j] = w1[i * HID + j] * s;
    }
    if (j < EMB) {
        float s = g2[j] * rsqrtf(v2[j] + BN_EPS);
        g_b2[j] = be2[j] - m2[j] * s;
        for (int i = 0; i < HID; i++)
            g_w2s[i * EMB + j] = w2[i * EMB + j] * s;
    }
}

// ---------------------------------------------------------------------------
// Broadcast-bias init: out[i*D + j] = bias[j]   (D multiple of 4)
// ---------------------------------------------------------------------------
__global__ void init_bias_kernel(float* __restrict__ out, const float* __restrict__ bias,
                                 int rows, int D) {
    int total4 = rows * (D >> 2);
    int i = blockIdx.x * blockDim.x + threadIdx.x;
    if (i < total4) {
        int j4 = i % (D >> 2);
        ((float4*)out)[i] = ((const float4*)bias)[j4];
    }
}

// ---------------------------------------------------------------------------
// Tiled fp32 GEMM: C[M,N] = op(A)[M,K] @ B[K,N]   (op = identity or ReLU)
// 256 threads, BM x BN tile, TM x TN per-thread microtile.
// ---------------------------------------------------------------------------
template<int BM, int BN, int BK, int TM, int TN, bool RELUA>
__global__ __launch_bounds__(256)
void sgemm_kernel(const float* __restrict__ A, const float* __restrict__ B,
                  float* __restrict__ C, int M, int K, int N) {
    __shared__ float As[BK][BM];
    __shared__ float Bs[BK][BN];

    const int tid = threadIdx.x;
    const int tx  = tid % (BN / TN);   // 16 columns of threads
    const int ty  = tid / (BN / TN);   // 16 rows of threads
    const int m0  = blockIdx.x * BM;
    const int n0  = blockIdx.y * BN;

    float acc[TM][TN];
#pragma unroll
    for (int i = 0; i < TM; i++)
#pragma unroll
        for (int j = 0; j < TN; j++) acc[i][j] = 0.f;

    for (int k0 = 0; k0 < K; k0 += BK) {
        // Load A tile (BM x BK), transposed into As[k][m], with row guard + optional ReLU
#pragma unroll
        for (int i = tid; i < BM * BK; i += 256) {
            int r = i / BK, c = i % BK;
            int gr = m0 + r;
            float v = (gr < M) ? A[(size_t)gr * K + k0 + c] : 0.f;
            if (RELUA) v = fmaxf(v, 0.f);
            As[c][r] = v;
        }
        // Load B tile (BK x BN)
#pragma unroll
        for (int i = tid; i < BK * BN; i += 256) {
            int kk = i / BN, nn = i % BN;
            Bs[kk][nn] = B[(size_t)(k0 + kk) * N + n0 + nn];
        }
        __syncthreads();

#pragma unroll
        for (int k = 0; k < BK; k++) {
            float a[TM], b[TN];
#pragma unroll
            for (int i = 0; i < TM; i += 4) {
                float4 t = *(const float4*)&As[k][ty * TM + i];
                a[i] = t.x; a[i+1] = t.y; a[i+2] = t.z; a[i+3] = t.w;
            }
#pragma unroll
            for (int j = 0; j < TN; j += 4) {
                float4 t = *(const float4*)&Bs[k][tx * TN + j];
                b[j] = t.x; b[j+1] = t.y; b[j+2] = t.z; b[j+3] = t.w;
            }
#pragma unroll
            for (int i = 0; i < TM; i++)
#pragma unroll
                for (int j = 0; j < TN; j++)
                    acc[i][j] = fmaf(a[i], b[j], acc[i][j]);
        }
        __syncthreads();
    }

    // Epilogue
#pragma unroll
    for (int i = 0; i < TM; i++) {
        int gr = m0 + ty * TM + i;
        if (gr < M) {
#pragma unroll
            for (int j = 0; j < TN; j += 4) {
                float4 t = make_float4(acc[i][j], acc[i][j+1], acc[i][j+2], acc[i][j+3]);
                *(float4*)&C[(size_t)gr * N + n0 + tx * TN + j] = t;
            }
        }
    }
}

// ---------------------------------------------------------------------------
// SpMM scatter, D=256: one warp per edge, 2 x float4 per lane, red.v4
// ---------------------------------------------------------------------------
__global__ void spmm256_kernel(const int* __restrict__ rows, const int* __restrict__ cols,
                               const float* __restrict__ vals, const float* __restrict__ src,
                               float* out, int E) {
    int w = (blockIdx.x * blockDim.x + threadIdx.x) >> 5;
    int lane = threadIdx.x & 31;
    if (w >= E) return;
    int r = rows[w], c = cols[w];
    float v = vals[w];
    const float4* s = (const float4*)(src + (size_t)c * 256);
    float* d = out + (size_t)r * 256;
#pragma unroll
    for (int i = 0; i < 2; i++) {
        int idx = lane + 32 * i;
        float4 a = __ldg(&s[idx]);
        red_add_v4(d + 4 * idx, v * a.x, v * a.y, v * a.z, v * a.w);
    }
}

// ---------------------------------------------------------------------------
// SpMM scatter, D=64: 16 lanes per edge, 1 x float4 per lane, red.v4
// ---------------------------------------------------------------------------
__global__ void spmm64_kernel(const int* __restrict__ rows, const int* __restrict__ cols,
                              const float* __restrict__ vals, const float* __restrict__ src,
                              float* out, int E) {
    int t = blockIdx.x * blockDim.x + threadIdx.x;
    int e = t >> 4;
    int l = t & 15;
    if (e >= E) return;
    int r = rows[e], c = cols[e];
    float v = vals[e];
    const float4* s = (const float4*)(src + (size_t)c * 64);
    float4 a = __ldg(&s[l]);
    red_add_v4(out + (size_t)r * 64 + 4 * l, v * a.x, v * a.y, v * a.z, v * a.w);
}

// ---------------------------------------------------------------------------
// Launch
// ---------------------------------------------------------------------------
extern "C" void kernel_launch(void* const* d_in, const int* in_sizes, int n_in,
                              void* d_out, int out_size) {
    const float* x        = (const float*)d_in[0];
    const int*   edge_row = (const int*)  d_in[1];
    const int*   edge_col = (const int*)  d_in[2];
    const float* edge_val = (const float*)d_in[3];
    const float* w1       = (const float*)d_in[4];
    const float* w2       = (const float*)d_in[5];
    const float* gamma1   = (const float*)d_in[6];
    const float* beta1    = (const float*)d_in[7];
    const float* mean1    = (const float*)d_in[8];
    const float* var1     = (const float*)d_in[9];
    const float* gamma2   = (const float*)d_in[10];
    const float* beta2    = (const float*)d_in[11];
    const float* mean2    = (const float*)d_in[12];
    const float* var2     = (const float*)d_in[13];
    float* out = (float*)d_out;

    const int M = NN;
    const int E = in_sizes[1];

    // Resolve device-global addresses (kernels reference them directly; we need
    // pointers only for passing between kernels)
    // (device globals are directly addressable inside kernels; use a tiny helper
    //  pattern: pass via pointers obtained by referencing the symbols in kernels)

    // 0) fold BN into weights/biases
    prep_kernel<<<1, 256>>>(w1, w2, gamma1, beta1, mean1, var1,
                            gamma2, beta2, mean2, var2);

    // helpers to get raw pointers to device globals on the host side:
    // we simply launch kernels that take them implicitly; for GEMM/SpMM we need
    // the addresses, so pass via small wrapper kernels is overkill — instead use
    // cudaGetSymbolAddress-free approach: kernels below take pointers, so grab
    // symbol addresses once per launch (cheap host-side, graph-capturable since
    // it's not a stream op... but to stay strictly capture-safe we cache them).
    static float *p_xw1 = nullptr, *p_h = nullptr, *p_hw2 = nullptr,
                 *p_w1s = nullptr, *p_w2s = nullptr, *p_b1 = nullptr, *p_b2 = nullptr;
    if (!p_xw1) {
        cudaGetSymbolAddress((void**)&p_xw1, g_xw1);
        cudaGetSymbolAddress((void**)&p_h,   g_h);
        cudaGetSymbolAddress((void**)&p_hw2, g_hw2);
        cudaGetSymbolAddress((void**)&p_w1s, g_w1s);
        cudaGetSymbolAddress((void**)&p_w2s, g_w2s);
        cudaGetSymbolAddress((void**)&p_b1,  g_b1);
        cudaGetSymbolAddress((void**)&p_b2,  g_b2);
    }

    // 1) xw1 = x @ w1'
    {
        dim3 grid((M + 127) / 128, HID / 128);
        sgemm_kernel<128, 128, 8, 8, 8, false><<<grid, 256>>>(x, p_w1s, p_xw1, M, IN_DIM, HID);
    }

    // 2) h = b1 (broadcast)
    {
        int total4 = M * (HID / 4);
        init_bias_kernel<<<(total4 + 255) / 256, 256>>>(p_h, p_b1, M, HID);
    }

    // 3) h += scatter(edge_val * xw1[col])  -> h is BN1 output (pre-ReLU)
    {
        long long threads = (long long)E * 32;
        spmm256_kernel<<<(unsigned)((threads + 255) / 256), 256>>>(
            edge_row, edge_col, edge_val, p_xw1, p_h, E);
    }

    // 4) hw2 = relu(h) @ w2'
    {
        dim3 grid((M + 127) / 128, 1);
        sgemm_kernel<128, 64, 8, 8, 4, true><<<grid, 256>>>(p_h, p_w2s, p_hw2, M, HID, EMB);
    }

    // 5) out = b2 (broadcast)
    {
        int total4 = M * (EMB / 4);
        init_bias_kernel<<<(total4 + 255) / 256, 256>>>(out, p_b2, M, EMB);
    }

    // 6) out += scatter(edge_val * hw2[col])  -> out is final BN2 output
    {
        long long threads = (long long)E * 16;
        spmm64_kernel<<<(unsigned)((threads + 255) / 256), 256>>>(
            edge_row, edge_col, edge_val, p_hw2, out, E);
    }
}

// round 3
// speedup vs baseline: 1.7066x; 1.7066x over previous
#include <cuda_runtime.h>
#include <cstdint>

// Problem constants (fixed by the reference)
#define NN      100000
#define IN_DIM  256
#define HID     256
#define EMB     64
#define E_MAX   3200000
#define BN_EPS  1e-3f
#define NB_SCAN ((NN + 1023) / 1024)   // 98

// ---------------------------------------------------------------------------
// Scratch (device globals: no runtime allocation allowed)
// ---------------------------------------------------------------------------
__device__ float g_xw1[(size_t)NN * HID];   // x @ w1'  (102.4 MB)
__device__ float g_h  [(size_t)NN * HID];   // relu(BN1 out)  (102.4 MB)
__device__ float g_hw2[(size_t)NN * EMB];   // h @ w2'  (25.6 MB)
__device__ float g_w1s[IN_DIM * HID];
__device__ float g_w2s[HID * EMB];
__device__ float g_b1[HID];
__device__ float g_b2[EMB];

// CSR build scratch
__device__ int  g_cnt[NN];          // per-row edge counts
__device__ int  g_excl[NN];         // intra-block exclusive scan
__device__ int  g_bsum[256];        // per-block sums
__device__ int  g_bsum2[256];       // scanned block sums
__device__ int  g_rowptr[NN + 1];
__device__ int  g_roff[NN];         // atomic cursors for scatter
__device__ int2 g_edges[E_MAX];     // (col, val_bits) sorted by row

// ---------------------------------------------------------------------------
// Prep: fold BN scale into weight columns, compute bias vectors
// ---------------------------------------------------------------------------
__global__ void prep_kernel(const float* __restrict__ w1, const float* __restrict__ w2,
                            const float* __restrict__ g1, const float* __restrict__ be1,
                            const float* __restrict__ m1, const float* __restrict__ v1,
                            const float* __restrict__ g2, const float* __restrict__ be2,
                            const float* __restrict__ m2, const float* __restrict__ v2) {
    int j = threadIdx.x;
    if (j < HID) {
        float s = g1[j] * rsqrtf(v1[j] + BN_EPS);
        g_b1[j] = be1[j] - m1[j] * s;
        for (int i = 0; i < IN_DIM; i++)
            g_w1s[i * HID + j] = w1[i * HID + j] * s;
    }
    if (j < EMB) {
        float s = g2[j] * rsqrtf(v2[j] + BN_EPS);
        g_b2[j] = be2[j] - m2[j] * s;
        for (int i = 0; i < HID; i++)
            g_w2s[i * EMB + j] = w2[i * EMB + j] * s;
    }
}

// ---------------------------------------------------------------------------
// CSR construction
// ---------------------------------------------------------------------------
__global__ void hist_kernel(const int* __restrict__ rows, int E) {
    int i = blockIdx.x * blockDim.x + threadIdx.x;
    if (i < E) atomicAdd(&g_cnt[rows[i]], 1);
}

__global__ __launch_bounds__(1024) void scan1_kernel(int n) {
    __shared__ int sh[1024];
    int gid = blockIdx.x * 1024 + threadIdx.x;
    int v = (gid < n) ? g_cnt[gid] : 0;
    sh[threadIdx.x] = v;
    __syncthreads();
#pragma unroll
    for (int off = 1; off < 1024; off <<= 1) {
        int t = (threadIdx.x >= off) ? sh[threadIdx.x - off] : 0;
        __syncthreads();
        sh[threadIdx.x] += t;
        __syncthreads();
    }
    if (gid < n) g_excl[gid] = sh[threadIdx.x] - v;
    if (threadIdx.x == 1023) g_bsum[blockIdx.x] = sh[1023];
}

__global__ void scan2_kernel(int nb) {
    if (threadIdx.x == 0) {
        int acc = 0;
        for (int i = 0; i < nb; i++) {
            g_bsum2[i] = acc;
            acc += g_bsum[i];
        }
    }
}

__global__ void scan3_kernel(int n, int E) {
    int gid = blockIdx.x * blockDim.x + threadIdx.x;
    if (gid < n) {
        int p = g_excl[gid] + g_bsum2[gid >> 10];
        g_rowptr[gid] = p;
        g_roff[gid] = p;
    }
    if (gid == 0) g_rowptr[n] = E;
}

__global__ void scatter_kernel(const int* __restrict__ rows, const int* __restrict__ cols,
                               const float* __restrict__ vals, int E) {
    int i = blockIdx.x * blockDim.x + threadIdx.x;
    if (i < E) {
        int r = rows[i];
        int p = atomicAdd(&g_roff[r], 1);
        g_edges[p] = make_int2(cols[i], __float_as_int(vals[i]));
    }
}

// ---------------------------------------------------------------------------
// Tiled fp32 GEMM: C[M,N] = A[M,K] @ B[K,N]
// ---------------------------------------------------------------------------
template<int BM, int BN, int BK, int TM, int TN>
__global__ __launch_bounds__(256)
void sgemm_kernel(const float* __restrict__ A, const float* __restrict__ B,
                  float* __restrict__ C, int M, int K, int N) {
    __shared__ float As[BK][BM];
    __shared__ float Bs[BK][BN];

    const int tid = threadIdx.x;
    const int tx  = tid % (BN / TN);
    const int ty  = tid / (BN / TN);
    const int m0  = blockIdx.x * BM;
    const int n0  = blockIdx.y * BN;

    float acc[TM][TN];
#pragma unroll
    for (int i = 0; i < TM; i++)
#pragma unroll
        for (int j = 0; j < TN; j++) acc[i][j] = 0.f;

    for (int k0 = 0; k0 < K; k0 += BK) {
#pragma unroll
        for (int i = tid; i < BM * BK; i += 256) {
            int r = i / BK, c = i % BK;
            int gr = m0 + r;
            As[c][r] = (gr < M) ? A[(size_t)gr * K + k0 + c] : 0.f;
        }
#pragma unroll
        for (int i = tid; i < BK * BN; i += 256) {
            int kk = i / BN, nn = i % BN;
            Bs[kk][nn] = B[(size_t)(k0 + kk) * N + n0 + nn];
        }
        __syncthreads();

#pragma unroll
        for (int k = 0; k < BK; k++) {
            float a[TM], b[TN];
#pragma unroll
            for (int i = 0; i < TM; i += 4) {
                float4 t = *(const float4*)&As[k][ty * TM + i];
                a[i] = t.x; a[i+1] = t.y; a[i+2] = t.z; a[i+3] = t.w;
            }
#pragma unroll
            for (int j = 0; j < TN; j += 4) {
                float4 t = *(const float4*)&Bs[k][tx * TN + j];
                b[j] = t.x; b[j+1] = t.y; b[j+2] = t.z; b[j+3] = t.w;
            }
#pragma unroll
            for (int i = 0; i < TM; i++)
#pragma unroll
                for (int j = 0; j < TN; j++)
                    acc[i][j] = fmaf(a[i], b[j], acc[i][j]);
        }
        __syncthreads();
    }

#pragma unroll
    for (int i = 0; i < TM; i++) {
        int gr = m0 + ty * TM + i;
        if (gr < M) {
#pragma unroll
            for (int j = 0; j < TN; j += 4) {
                float4 t = make_float4(acc[i][j], acc[i][j+1], acc[i][j+2], acc[i][j+3]);
                *(float4*)&C[(size_t)gr * N + n0 + tx * TN + j] = t;
            }
        }
    }
}

// ---------------------------------------------------------------------------
// CSR SpMM, D=256: one warp per row; register accumulation (init = b1);
// stores relu(acc) directly. No atomics, one write per output element.
// ---------------------------------------------------------------------------
__global__ __launch_bounds__(256)
void spmm256_csr_kernel(const float* __restrict__ src, float* __restrict__ out, int n) {
    int row  = (blockIdx.x * blockDim.x + threadIdx.x) >> 5;
    int lane = threadIdx.x & 31;
    if (row >= n) return;

    int start = g_rowptr[row];
    int end   = g_rowptr[row + 1];

    const float4* b1 = (const float4*)g_b1;
    float4 acc0 = b1[lane];
    float4 acc1 = b1[lane + 32];

    int e = start;
    for (; e + 1 < end; e += 2) {
        int2 ed0 = g_edges[e];
        int2 ed1 = g_edges[e + 1];
        const float4* s0 = (const float4*)(src + (size_t)ed0.x * 256);
        const float4* s1 = (const float4*)(src + (size_t)ed1.x * 256);
        float v0 = __int_as_float(ed0.y);
        float v1 = __int_as_float(ed1.y);
        float4 a0 = __ldg(&s0[lane]);
        float4 a1 = __ldg(&s0[lane + 32]);
        float4 c0 = __ldg(&s1[lane]);
        float4 c1 = __ldg(&s1[lane + 32]);
        acc0.x = fmaf(v0, a0.x, acc0.x); acc0.y = fmaf(v0, a0.y, acc0.y);
        acc0.z = fmaf(v0, a0.z, acc0.z); acc0.w = fmaf(v0, a0.w, acc0.w);
        acc1.x = fmaf(v0, a1.x, acc1.x); acc1.y = fmaf(v0, a1.y, acc1.y);
        acc1.z = fmaf(v0, a1.z, acc1.z); acc1.w = fmaf(v0, a1.w, acc1.w);
        acc0.x = fmaf(v1, c0.x, acc0.x); acc0.y = fmaf(v1, c0.y, acc0.y);
        acc0.z = fmaf(v1, c0.z, acc0.z); acc0.w = fmaf(v1, c0.w, acc0.w);
        acc1.x = fmaf(v1, c1.x, acc1.x); acc1.y = fmaf(v1, c1.y, acc1.y);
        acc1.z = fmaf(v1, c1.z, acc1.z); acc1.w = fmaf(v1, c1.w, acc1.w);
    }
    if (e < end) {
        int2 ed = g_edges[e];
        const float4* s = (const float4*)(src + (size_t)ed.x * 256);
        float v = __int_as_float(ed.y);
        float4 a0 = __ldg(&s[lane]);
        float4 a1 = __ldg(&s[lane + 32]);
        acc0.x = fmaf(v, a0.x, acc0.x); acc0.y = fmaf(v, a0.y, acc0.y);
        acc0.z = fmaf(v, a0.z, acc0.z); acc0.w = fmaf(v, a0.w, acc0.w);
        acc1.x = fmaf(v, a1.x, acc1.x); acc1.y = fmaf(v, a1.y, acc1.y);
        acc1.z = fmaf(v, a1.z, acc1.z); acc1.w = fmaf(v, a1.w, acc1.w);
    }

    // ReLU in-place (this is layer-1's post-BN activation)
    acc0.x = fmaxf(acc0.x, 0.f); acc0.y = fmaxf(acc0.y, 0.f);
    acc0.z = fmaxf(acc0.z, 0.f); acc0.w = fmaxf(acc0.w, 0.f);
    acc1.x = fmaxf(acc1.x, 0.f); acc1.y = fmaxf(acc1.y, 0.f);
    acc1.z = fmaxf(acc1.z, 0.f); acc1.w = fmaxf(acc1.w, 0.f);

    float4* d = (float4*)(out + (size_t)row * 256);
    d[lane]      = acc0;
    d[lane + 32] = acc1;
}

// ---------------------------------------------------------------------------
// CSR SpMM, D=64: one warp per row; lane handles a float2 (init = b2).
// ---------------------------------------------------------------------------
__global__ __launch_bounds__(256)
void spmm64_csr_kernel(const float* __restrict__ src, float* __restrict__ out, int n) {
    int row  = (blockIdx.x * blockDim.x + threadIdx.x) >> 5;
    int lane = threadIdx.x & 31;
    if (row >= n) return;

    int start = g_rowptr[row];
    int end   = g_rowptr[row + 1];

    float2 acc = ((const float2*)g_b2)[lane];

    int e = start;
    for (; e + 1 < end; e += 2) {
        int2 ed0 = g_edges[e];
        int2 ed1 = g_edges[e + 1];
        float v0 = __int_as_float(ed0.y);
        float v1 = __int_as_float(ed1.y);
        float2 a = __ldg((const float2*)(src + (size_t)ed0.x * 64) + lane);
        float2 b = __ldg((const float2*)(src + (size_t)ed1.x * 64) + lane);
        acc.x = fmaf(v0, a.x, acc.x); acc.y = fmaf(v0, a.y, acc.y);
        acc.x = fmaf(v1, b.x, acc.x); acc.y = fmaf(v1, b.y, acc.y);
    }
    if (e < end) {
        int2 ed = g_edges[e];
        float v = __int_as_float(ed.y);
        float2 a = __ldg((const float2*)(src + (size_t)ed.x * 64) + lane);
        acc.x = fmaf(v, a.x, acc.x); acc.y = fmaf(v, a.y, acc.y);
    }

    ((float2*)(out + (size_t)row * 64))[lane] = acc;
}

// ---------------------------------------------------------------------------
// Launch
// ---------------------------------------------------------------------------
extern "C" void kernel_launch(void* const* d_in, const int* in_sizes, int n_in,
                              void* d_out, int out_size) {
    const float* x        = (const float*)d_in[0];
    const int*   edge_row = (const int*)  d_in[1];
    const int*   edge_col = (const int*)  d_in[2];
    const float* edge_val = (const float*)d_in[3];
    const float* w1       = (const float*)d_in[4];
    const float* w2       = (const float*)d_in[5];
    const float* gamma1   = (const float*)d_in[6];
    const float* beta1    = (const float*)d_in[7];
    const float* mean1    = (const float*)d_in[8];
    const float* var1     = (const float*)d_in[9];
    const float* gamma2   = (const float*)d_in[10];
    const float* beta2    = (const float*)d_in[11];
    const float* mean2    = (const float*)d_in[12];
    const float* var2     = (const float*)d_in[13];
    float* out = (float*)d_out;

    const int M = NN;
    const int E = in_sizes[1];

    static float *p_xw1 = nullptr, *p_h = nullptr, *p_hw2 = nullptr,
                 *p_w1s = nullptr, *p_w2s = nullptr;
    static int *p_cnt = nullptr;
    if (!p_xw1) {
        cudaGetSymbolAddress((void**)&p_xw1, g_xw1);
        cudaGetSymbolAddress((void**)&p_h,   g_h);
        cudaGetSymbolAddress((void**)&p_hw2, g_hw2);
        cudaGetSymbolAddress((void**)&p_w1s, g_w1s);
        cudaGetSymbolAddress((void**)&p_w2s, g_w2s);
        cudaGetSymbolAddress((void**)&p_cnt, g_cnt);
    }

    // 0) fold BN into weights/biases
    prep_kernel<<<1, 256>>>(w1, w2, gamma1, beta1, mean1, var1,
                            gamma2, beta2, mean2, var2);

    // --- CSR build ---
    cudaMemsetAsync(p_cnt, 0, NN * sizeof(int));
    hist_kernel<<<(E + 255) / 256, 256>>>(edge_row, E);
    scan1_kernel<<<NB_SCAN, 1024>>>(M);
    scan2_kernel<<<1, 32>>>(NB_SCAN);
    scan3_kernel<<<(M + 255) / 256, 256>>>(M, E);
    scatter_kernel<<<(E + 255) / 256, 256>>>(edge_row, edge_col, edge_val, E);

    // 1) xw1 = x @ w1'
    {
        dim3 grid((M + 127) / 128, HID / 128);
        sgemm_kernel<128, 128, 8, 8, 8><<<grid, 256>>>(x, p_w1s, p_xw1, M, IN_DIM, HID);
    }

    // 2) h = relu(b1 + A @ xw1)   (CSR gather, register accumulation)
    spmm256_csr_kernel<<<(M * 32 + 255) / 256, 256>>>(p_xw1, p_h, M);

    // 3) hw2 = h @ w2'
    {
        dim3 grid((M + 127) / 128, 1);
        sgemm_kernel<128, 64, 8, 8, 4><<<grid, 256>>>(p_h, p_w2s, p_hw2, M, HID, EMB);
    }

    // 4) out = b2 + A @ hw2
    spmm64_csr_kernel<<<(M * 32 + 255) / 256, 256>>>(p_hw2, out, M);
}

// round 6
// speedup vs baseline: 1.9270x; 1.1291x over previous
#include <cuda_runtime.h>
#include <cstdint>

// Problem constants (fixed by the reference)
#define NN      100000
#define IN_DIM  256
#define HID     256
#define EMB     64
#define E_MAX   3200000
#define BN_EPS  1e-3f
#define NB_SCAN ((NN + 1023) / 1024)   // 98

// ---------------------------------------------------------------------------
// Scratch (device globals: no runtime allocation allowed)
// ---------------------------------------------------------------------------
__device__ float g_xw1[(size_t)NN * HID];   // x @ w1'  (102.4 MB)
__device__ float g_h  [(size_t)NN * HID];   // relu(BN1 out)  (102.4 MB)
__device__ float g_hw2[(size_t)NN * EMB];   // h @ w2'  (25.6 MB)
__device__ float g_w1s[IN_DIM * HID];
__device__ float g_w2s[HID * EMB];
__device__ float g_b1[HID];
__device__ float g_b2[EMB];

// CSR build scratch
__device__ int  g_cnt[NN];
__device__ int  g_excl[NN];
__device__ int  g_bsum[128];
__device__ int  g_bsum2[128];
__device__ int  g_rowptr[NN + 1];
__device__ int  g_roff[NN];
__device__ int2 g_edges[E_MAX];     // (col, val_bits) sorted by row

// ---------------------------------------------------------------------------
// Prep: fold BN scale into weight columns, compute bias vectors.
// grid = IN_DIM blocks, 256 threads. Each block handles one row of w1s (and
// one row of w2s); block 0 also writes the bias vectors.
// ---------------------------------------------------------------------------
__global__ void prep_kernel(const float* __restrict__ w1, const float* __restrict__ w2,
                            const float* __restrict__ g1, const float* __restrict__ be1,
                            const float* __restrict__ m1, const float* __restrict__ v1,
                            const float* __restrict__ g2, const float* __restrict__ be2,
                            const float* __restrict__ m2, const float* __restrict__ v2) {
    int i = blockIdx.x;
    int j = threadIdx.x;
    float s1 = g1[j] * rsqrtf(v1[j] + BN_EPS);
    g_w1s[i * HID + j] = w1[i * HID + j] * s1;
    if (j < EMB) {
        float s2 = g2[j] * rsqrtf(v2[j] + BN_EPS);
        g_w2s[i * EMB + j] = w2[i * EMB + j] * s2;   // i ranges over HID == IN_DIM
        if (i == 0) g_b2[j] = be2[j] - m2[j] * s2;
    }
    if (i == 0) g_b1[j] = be1[j] - m1[j] * s1;
}

// ---------------------------------------------------------------------------
// CSR construction
// ---------------------------------------------------------------------------
__global__ void hist_kernel(const int* __restrict__ rows, int E) {
    int i = blockIdx.x * blockDim.x + threadIdx.x;
    if (i < E) atomicAdd(&g_cnt[rows[i]], 1);
}

__global__ __launch_bounds__(1024) void scan1_kernel(int n) {
    __shared__ int sh[1024];
    int gid = blockIdx.x * 1024 + threadIdx.x;
    int v = (gid < n) ? g_cnt[gid] : 0;
    sh[threadIdx.x] = v;
    __syncthreads();
#pragma unroll
    for (int off = 1; off < 1024; off <<= 1) {
        int t = (threadIdx.x >= off) ? sh[threadIdx.x - off] : 0;
        __syncthreads();
        sh[threadIdx.x] += t;
        __syncthreads();
    }
    if (gid < n) g_excl[gid] = sh[threadIdx.x] - v;
    if (threadIdx.x == 1023) g_bsum[blockIdx.x] = sh[1023];
}

__global__ void scan2_kernel(int nb) {
    __shared__ int sh[128];
    int t = threadIdx.x;
    int v = (t < nb) ? g_bsum[t] : 0;
    sh[t] = v;
    __syncthreads();
#pragma unroll
    for (int off = 1; off < 128; off <<= 1) {
        int u = (t >= off) ? sh[t - off] : 0;
        __syncthreads();
        sh[t] += u;
        __syncthreads();
    }
    if (t < nb) g_bsum2[t] = sh[t] - v;   // exclusive
}

__global__ void scan3_kernel(int n, int E) {
    int gid = blockIdx.x * blockDim.x + threadIdx.x;
    if (gid < n) {
        int p = g_excl[gid] + g_bsum2[gid >> 10];
        g_rowptr[gid] = p;
        g_roff[gid] = p;
    }
    if (gid == 0) g_rowptr[n] = E;
}

__global__ void scatter_kernel(const int* __restrict__ rows, const int* __restrict__ cols,
                               const float* __restrict__ vals, int E) {
    int i = blockIdx.x * blockDim.x + threadIdx.x;
    if (i < E) {
        int r = rows[i];
        int p = atomicAdd(&g_roff[r], 1);
        g_edges[p] = make_int2(cols[i], __float_as_int(vals[i]));
    }
}

// ---------------------------------------------------------------------------
// Double-buffered tiled fp32 GEMM: C[M,N] = A[M,K] @ B[K,N]
// 256 threads, 2-stage smem pipeline with register staging.
// CSA: use streaming loads (.cs) for A (read-once inputs).
// ---------------------------------------------------------------------------
template<int BM, int BN, int BK, int TM, int TN, bool CSA>
__global__ __launch_bounds__(256)
void sgemm_db_kernel(const float* __restrict__ A, const float* __restrict__ B,
                     float* __restrict__ C, int M, int K, int N) {
    __shared__ float As[2][BK][BM];
    __shared__ float Bs[2][BK][BN];

    const int tid = threadIdx.x;
    const int tx  = tid % (BN / TN);
    const int ty  = tid / (BN / TN);
    const int m0  = blockIdx.x * BM;
    const int n0  = blockIdx.y * BN;

    constexpr int A4 = BM * BK / 4;
    constexpr int B4 = BK * BN / 4;
    constexpr int RA = (A4 + 255) / 256;
    constexpr int RB = (B4 + 255) / 256;
    float4 ra[RA], rb[RB];

    const int NT = K / BK;

    auto loadA = [&](int t) {
#pragma unroll
        for (int u = 0; u < RA; u++) {
            int i = tid + u * 256;
            if (i < A4) {
                int row = i / (BK / 4), c4 = i % (BK / 4);
                int gr = m0 + row;
                if (gr < M) {
                    const float4* p = (const float4*)(A + (size_t)gr * K + t * BK + c4 * 4);
                    ra[u] = CSA ? __ldcs(p) : __ldg(p);
                } else {
                    ra[u] = make_float4(0.f, 0.f, 0.f, 0.f);
                }
            }
        }
    };
    auto loadB = [&](int t) {
#pragma unroll
        for (int u = 0; u < RB; u++) {
            int i = tid + u * 256;
            if (i < B4) {
                int kk = i / (BN / 4), n4 = i % (BN / 4);
                rb[u] = __ldg((const float4*)(B + (size_t)(t * BK + kk) * N + n0 + n4 * 4));
            }
        }
    };
    auto stageA = [&](int buf) {
#pragma unroll
        for (int u = 0; u < RA; u++) {
            int i = tid + u * 256;
            if (i < A4) {
                int row = i / (BK / 4), c4 = i % (BK / 4);
                As[buf][c4 * 4 + 0][row] = ra[u].x;
                As[buf][c4 * 4 + 1][row] = ra[u].y;
                As[buf][c4 * 4 + 2][row] = ra[u].z;
                As[buf][c4 * 4 + 3][row] = ra[u].w;
            }
        }
    };
    auto stageB = [&](int buf) {
#pragma unroll
        for (int u = 0; u < RB; u++) {
            int i = tid + u * 256;
            if (i < B4) {
                int kk = i / (BN / 4), n4 = i % (BN / 4);
                *(float4*)&Bs[buf][kk][n4 * 4] = rb[u];
            }
        }
    };

    float acc[TM][TN];
#pragma unroll
    for (int i = 0; i < TM; i++)
#pragma unroll
        for (int j = 0; j < TN; j++) acc[i][j] = 0.f;

    loadA(0); loadB(0);
    stageA(0); stageB(0);
    __syncthreads();

    for (int t = 0; t < NT; t++) {
        int buf = t & 1;
        if (t + 1 < NT) { loadA(t + 1); loadB(t + 1); }

#pragma unroll
        for (int k = 0; k < BK; k++) {
            float a[TM], b[TN];
#pragma unroll
            for (int i = 0; i < TM; i += 4) {
                float4 v = *(const float4*)&As[buf][k][ty * TM + i];
                a[i] = v.x; a[i+1] = v.y; a[i+2] = v.z; a[i+3] = v.w;
            }
#pragma unroll
            for (int j = 0; j < TN; j += 4) {
                float4 v = *(const float4*)&Bs[buf][k][tx * TN + j];
                b[j] = v.x; b[j+1] = v.y; b[j+2] = v.z; b[j+3] = v.w;
            }
#pragma unroll
            for (int i = 0; i < TM; i++)
#pragma unroll
                for (int j = 0; j < TN; j++)
                    acc[i][j] = fmaf(a[i], b[j], acc[i][j]);
        }

        if (t + 1 < NT) {
            stageA(buf ^ 1); stageB(buf ^ 1);
            __syncthreads();
        }
    }

#pragma unroll
    for (int i = 0; i < TM; i++) {
        int gr = m0 + ty * TM + i;
        if (gr < M) {
#pragma unroll
            for (int j = 0; j < TN; j += 4) {
                float4 v = make_float4(acc[i][j], acc[i][j+1], acc[i][j+2], acc[i][j+3]);
                *(float4*)&C[(size_t)gr * N + n0 + tx * TN + j] = v;
            }
        }
    }
}

// ---------------------------------------------------------------------------
// CSR SpMM, D=256: one warp per row; register accumulation (init = b1);
// stores relu(acc). Edges: streaming loads; output: streaming stores; the
// gather table stays L2-resident.
// ---------------------------------------------------------------------------
__global__ __launch_bounds__(256)
void spmm256_csr_kernel(const float* __restrict__ src, float* __restrict__ out, int n) {
    int row  = (blockIdx.x * blockDim.x + threadIdx.x) >> 5;
    int lane = threadIdx.x & 31;
    if (row >= n) return;

    int start = g_rowptr[row];
    int end   = g_rowptr[row + 1];

    const float4* b1 = (const float4*)g_b1;
    float4 acc0 = b1[lane];
    float4 acc1 = b1[lane + 32];

    int e = start;
    for (; e + 1 < end; e += 2) {
        int2 ed0 = __ldcs(&g_edges[e]);
        int2 ed1 = __ldcs(&g_edges[e + 1]);
        const float4* s0 = (const float4*)(src + (size_t)ed0.x * 256);
        const float4* s1 = (const float4*)(src + (size_t)ed1.x * 256);
        float v0 = __int_as_float(ed0.y);
        float v1 = __int_as_float(ed1.y);
        float4 a0 = __ldg(&s0[lane]);
        float4 a1 = __ldg(&s0[lane + 32]);
        float4 c0 = __ldg(&s1[lane]);
        float4 c1 = __ldg(&s1[lane + 32]);
        acc0.x = fmaf(v0, a0.x, acc0.x); acc0.y = fmaf(v0, a0.y, acc0.y);
        acc0.z = fmaf(v0, a0.z, acc0.z); acc0.w = fmaf(v0, a0.w, acc0.w);
        acc1.x = fmaf(v0, a1.x, acc1.x); acc1.y = fmaf(v0, a1.y, acc1.y);
        acc1.z = fmaf(v0, a1.z, acc1.z); acc1.w = fmaf(v0, a1.w, acc1.w);
        acc0.x = fmaf(v1, c0.x, acc0.x); acc0.y = fmaf(v1, c0.y, acc0.y);
        acc0.z = fmaf(v1, c0.z, acc0.z); acc0.w = fmaf(v1, c0.w, acc0.w);
        acc1.x = fmaf(v1, c1.x, acc1.x); acc1.y = fmaf(v1, c1.y, acc1.y);
        acc1.z = fmaf(v1, c1.z, acc1.z); acc1.w = fmaf(v1, c1.w, acc1.w);
    }
    if (e < end) {
        int2 ed = __ldcs(&g_edges[e]);
        const float4* s = (const float4*)(src + (size_t)ed.x * 256);
        float v = __int_as_float(ed.y);
        float4 a0 = __ldg(&s[lane]);
        float4 a1 = __ldg(&s[lane + 32]);
        acc0.x = fmaf(v, a0.x, acc0.x); acc0.y = fmaf(v, a0.y, acc0.y);
        acc0.z = fmaf(v, a0.z, acc0.z); acc0.w = fmaf(v, a0.w, acc0.w);
        acc1.x = fmaf(v, a1.x, acc1.x); acc1.y = fmaf(v, a1.y, acc1.y);
        acc1.z = fmaf(v, a1.z, acc1.z); acc1.w = fmaf(v, a1.w, acc1.w);
    }

    acc0.x = fmaxf(acc0.x, 0.f); acc0.y = fmaxf(acc0.y, 0.f);
    acc0.z = fmaxf(acc0.z, 0.f); acc0.w = fmaxf(acc0.w, 0.f);
    acc1.x = fmaxf(acc1.x, 0.f); acc1.y = fmaxf(acc1.y, 0.f);
    acc1.z = fmaxf(acc1.z, 0.f); acc1.w = fmaxf(acc1.w, 0.f);

    float4* d = (float4*)(out + (size_t)row * 256);
    __stcs(&d[lane],      acc0);
    __stcs(&d[lane + 32], acc1);
}

// ---------------------------------------------------------------------------
// CSR SpMM, D=64: one warp per row; lane handles a float2 (init = b2).
// ---------------------------------------------------------------------------
__global__ __launch_bounds__(256)
void spmm64_csr_kernel(const float* __restrict__ src, float* __restrict__ out, int n) {
    int row  = (blockIdx.x * blockDim.x + threadIdx.x) >> 5;
    int lane = threadIdx.x & 31;
    if (row >= n) return;

    int start = g_rowptr[row];
    int end   = g_rowptr[row + 1];

    float2 acc = ((const float2*)g_b2)[lane];

    int e = start;
    for (; e + 1 < end; e += 2) {
        int2 ed0 = __ldcs(&g_edges[e]);
        int2 ed1 = __ldcs(&g_edges[e + 1]);
        float v0 = __int_as_float(ed0.y);
        float v1 = __int_as_float(ed1.y);
        float2 a = __ldg((const float2*)(src + (size_t)ed0.x * 64) + lane);
        float2 b = __ldg((const float2*)(src + (size_t)ed1.x * 64) + lane);
        acc.x = fmaf(v0, a.x, acc.x); acc.y = fmaf(v0, a.y, acc.y);
        acc.x = fmaf(v1, b.x, acc.x); acc.y = fmaf(v1, b.y, acc.y);
    }
    if (e < end) {
        int2 ed = __ldcs(&g_edges[e]);
        float v = __int_as_float(ed.y);
        float2 a = __ldg((const float2*)(src + (size_t)ed.x * 64) + lane);
        acc.x = fmaf(v, a.x, acc.x); acc.y = fmaf(v, a.y, acc.y);
    }

    __stcs((float2*)(out + (size_t)row * 64) + lane, acc);
}

// ---------------------------------------------------------------------------
// Launch: CSR build (side stream) runs concurrently with prep+GEMM1 (main).
// ---------------------------------------------------------------------------
extern "C" void kernel_launch(void* const* d_in, const int* in_sizes, int n_in,
                              void* d_out, int out_size) {
    const float* x        = (const float*)d_in[0];
    const int*   edge_row = (const int*)  d_in[1];
    const int*   edge_col = (const int*)  d_in[2];
    const float* edge_val = (const float*)d_in[3];
    const float* w1       = (const float*)d_in[4];
    const float* w2       = (const float*)d_in[5];
    const float* gamma1   = (const float*)d_in[6];
    const float* beta1    = (const float*)d_in[7];
    const float* mean1    = (const float*)d_in[8];
    const float* var1     = (const float*)d_in[9];
    const float* gamma2   = (const float*)d_in[10];
    const float* beta2    = (const float*)d_in[11];
    const float* mean2    = (const float*)d_in[12];
    const float* var2     = (const float*)d_in[13];
    float* out = (float*)d_out;

    const int M = NN;
    const int E = in_sizes[1];

    static float *p_xw1 = nullptr, *p_h = nullptr, *p_hw2 = nullptr,
                 *p_w1s = nullptr, *p_w2s = nullptr;
    static int *p_cnt = nullptr;
    static cudaStream_t s_side = nullptr;
    static cudaEvent_t ev_fork = nullptr, ev_join = nullptr;
    if (!p_xw1) {
        cudaGetSymbolAddress((void**)&p_xw1, g_xw1);
        cudaGetSymbolAddress((void**)&p_h,   g_h);
        cudaGetSymbolAddress((void**)&p_hw2, g_hw2);
        cudaGetSymbolAddress((void**)&p_w1s, g_w1s);
        cudaGetSymbolAddress((void**)&p_w2s, g_w2s);
        cudaGetSymbolAddress((void**)&p_cnt, g_cnt);
        cudaStreamCreateWithFlags(&s_side, cudaStreamNonBlocking);
        cudaEventCreateWithFlags(&ev_fork, cudaEventDisableTiming);
        cudaEventCreateWithFlags(&ev_join, cudaEventDisableTiming);
    }

    // --- fork: CSR build on side stream ---
    cudaEventRecord(ev_fork, 0);
    cudaStreamWaitEvent(s_side, ev_fork, 0);
    cudaMemsetAsync(p_cnt, 0, NN * sizeof(int), s_side);
    hist_kernel<<<(E + 255) / 256, 256, 0, s_side>>>(edge_row, E);
    scan1_kernel<<<NB_SCAN, 1024, 0, s_side>>>(M);
    scan2_kernel<<<1, 128, 0, s_side>>>(NB_SCAN);
    scan3_kernel<<<(M + 255) / 256, 256, 0, s_side>>>(M, E);
    scatter_kernel<<<(E + 255) / 256, 256, 0, s_side>>>(edge_row, edge_col, edge_val, E);
    cudaEventRecord(ev_join, s_side);

    // --- main stream: prep + GEMM1 (independent of CSR) ---
    prep_kernel<<<IN_DIM, 256>>>(w1, w2, gamma1, beta1, mean1, var1,
                                 gamma2, beta2, mean2, var2);
    {
        dim3 grid((M + 127) / 128, HID / 128);
        sgemm_db_kernel<128, 128, 8, 8, 8, false><<<grid, 256>>>(x, p_w1s, p_xw1, M, IN_DIM, HID);
    }

    // --- join, then the dependent chain ---
    cudaStreamWaitEvent(0, ev_join, 0);
    spmm256_csr_kernel<<<(M * 32 + 255) / 256, 256>>>(p_xw1, p_h, M);
    {
        dim3 grid((M + 127) / 128, 1);
        sgemm_db_kernel<128, 64, 8, 8, 4, true><<<grid, 256>>>(p_h, p_w2s, p_hw2, M, HID, EMB);
    }
    spmm64_csr_kernel<<<(M * 32 + 255) / 256, 256>>>(p_hw2, out, M);
}

// round 8
// speedup vs baseline: 2.3039x; 1.1956x over previous
#include <cuda_runtime.h>
#include <cuda_fp16.h>
#include <cstdint>

// Problem constants (fixed by the reference)
#define NN      100000
#define IN_DIM  256
#define HID     256
#define EMB     64
#define E_MAX   3200000
#define BN_EPS  1e-3f
#define NB_SCAN ((NN + 1023) / 1024)   // 98

// ---------------------------------------------------------------------------
// Scratch (device globals: no runtime allocation allowed)
// ---------------------------------------------------------------------------
__device__ __half g_xw1h[(size_t)NN * HID];  // x @ w1'  in fp16 (51.2 MB, L2-resident)
__device__ float  g_h  [(size_t)NN * HID];   // relu(BN1 out) fp32 (102.4 MB)
__device__ __half g_hw2h[(size_t)NN * EMB];  // h @ w2'  in fp16 (12.8 MB)
__device__ float  g_w1s[IN_DIM * HID];
__device__ float  g_w2s[HID * EMB];
__device__ float  g_b1[HID];
__device__ float  g_b2[EMB];

// CSR build scratch
__device__ int  g_cnt[NN];
__device__ int  g_excl[NN];
__device__ int  g_bsum[128];
__device__ int  g_bsum2[128];
__device__ int  g_rowptr[NN + 1];
__device__ int  g_roff[NN];
__device__ int2 g_edges[E_MAX];     // (col, val_bits) sorted by row

// ---------------------------------------------------------------------------
// Prep: fold BN scale into weight columns, compute bias vectors.
// ---------------------------------------------------------------------------
__global__ void prep_kernel(const float* __restrict__ w1, const float* __restrict__ w2,
                            const float* __restrict__ g1, const float* __restrict__ be1,
                            const float* __restrict__ m1, const float* __restrict__ v1,
                            const float* __restrict__ g2, const float* __restrict__ be2,
                            const float* __restrict__ m2, const float* __restrict__ v2) {
    int i = blockIdx.x;
    int j = threadIdx.x;
    float s1 = g1[j] * rsqrtf(v1[j] + BN_EPS);
    g_w1s[i * HID + j] = w1[i * HID + j] * s1;
    if (j < EMB) {
        float s2 = g2[j] * rsqrtf(v2[j] + BN_EPS);
        g_w2s[i * EMB + j] = w2[i * EMB + j] * s2;
        if (i == 0) g_b2[j] = be2[j] - m2[j] * s2;
    }
    if (i == 0) g_b1[j] = be1[j] - m1[j] * s1;
}

// ---------------------------------------------------------------------------
// CSR construction
// ---------------------------------------------------------------------------
__global__ void hist_kernel(const int* __restrict__ rows, int E) {
    int i = blockIdx.x * blockDim.x + threadIdx.x;
    if (i < E) atomicAdd(&g_cnt[rows[i]], 1);
}

__global__ __launch_bounds__(1024) void scan1_kernel(int n) {
    __shared__ int sh[1024];
    int gid = blockIdx.x * 1024 + threadIdx.x;
    int v = (gid < n) ? g_cnt[gid] : 0;
    sh[threadIdx.x] = v;
    __syncthreads();
#pragma unroll
    for (int off = 1; off < 1024; off <<= 1) {
        int t = (threadIdx.x >= off) ? sh[threadIdx.x - off] : 0;
        __syncthreads();
        sh[threadIdx.x] += t;
        __syncthreads();
    }
    if (gid < n) g_excl[gid] = sh[threadIdx.x] - v;
    if (threadIdx.x == 1023) g_bsum[blockIdx.x] = sh[1023];
}

__global__ void scan2_kernel(int nb) {
    __shared__ int sh[128];
    int t = threadIdx.x;
    int v = (t < nb) ? g_bsum[t] : 0;
    sh[t] = v;
    __syncthreads();
#pragma unroll
    for (int off = 1; off < 128; off <<= 1) {
        int u = (t >= off) ? sh[t - off] : 0;
        __syncthreads();
        sh[t] += u;
        __syncthreads();
    }
    if (t < nb) g_bsum2[t] = sh[t] - v;   // exclusive
}

__global__ void scan3_kernel(int n, int E) {
    int gid = blockIdx.x * blockDim.x + threadIdx.x;
    if (gid < n) {
        int p = g_excl[gid] + g_bsum2[gid >> 10];
        g_rowptr[gid] = p;
        g_roff[gid] = p;
    }
    if (gid == 0) g_rowptr[n] = E;
}

__global__ void scatter_kernel(const int* __restrict__ rows, const int* __restrict__ cols,
                               const float* __restrict__ vals, int E) {
    int i = blockIdx.x * blockDim.x + threadIdx.x;
    if (i < E) {
        int r = rows[i];
        int p = atomicAdd(&g_roff[r], 1);
        g_edges[p] = make_int2(cols[i], __float_as_int(vals[i]));
    }
}

// ---------------------------------------------------------------------------
// Double-buffered tiled fp32 GEMM: C[M,N] = A[M,K] @ B[K,N]
// Compute in fp32; optional fp16 output (storage rounding only).
// CSA: streaming loads for A (read-once inputs).
// ---------------------------------------------------------------------------
template<int BM, int BN, int BK, int TM, int TN, bool CSA, bool HOUT>
__global__ __launch_bounds__(256)
void sgemm_db_kernel(const float* __restrict__ A, const float* __restrict__ B,
                     void* __restrict__ Cv, int M, int K, int N) {
    __shared__ float As[2][BK][BM];
    __shared__ float Bs[2][BK][BN];

    const int tid = threadIdx.x;
    const int tx  = tid % (BN / TN);
    const int ty  = tid / (BN / TN);
    const int m0  = blockIdx.x * BM;
    const int n0  = blockIdx.y * BN;

    constexpr int A4 = BM * BK / 4;
    constexpr int B4 = BK * BN / 4;
    constexpr int RA = (A4 + 255) / 256;
    constexpr int RB = (B4 + 255) / 256;
    float4 ra[RA], rb[RB];

    const int NT = K / BK;

    auto loadA = [&](int t) {
#pragma unroll
        for (int u = 0; u < RA; u++) {
            int i = tid + u * 256;
            if (i < A4) {
                int row = i / (BK / 4), c4 = i % (BK / 4);
                int gr = m0 + row;
                if (gr < M) {
                    const float4* p = (const float4*)(A + (size_t)gr * K + t * BK + c4 * 4);
                    ra[u] = CSA ? __ldcs(p) : __ldg(p);
                } else {
                    ra[u] = make_float4(0.f, 0.f, 0.f, 0.f);
                }
            }
        }
    };
    auto loadB = [&](int t) {
#pragma unroll
        for (int u = 0; u < RB; u++) {
            int i = tid + u * 256;
            if (i < B4) {
                int kk = i / (BN / 4), n4 = i % (BN / 4);
                rb[u] = __ldg((const float4*)(B + (size_t)(t * BK + kk) * N + n0 + n4 * 4));
            }
        }
    };
    auto stageA = [&](int buf) {
#pragma unroll
        for (int u = 0; u < RA; u++) {
            int i = tid + u * 256;
            if (i < A4) {
                int row = i / (BK / 4), c4 = i % (BK / 4);
                As[buf][c4 * 4 + 0][row] = ra[u].x;
                As[buf][c4 * 4 + 1][row] = ra[u].y;
                As[buf][c4 * 4 + 2][row] = ra[u].z;
                As[buf][c4 * 4 + 3][row] = ra[u].w;
            }
        }
    };
    auto stageB = [&](int buf) {
#pragma unroll
        for (int u = 0; u < RB; u++) {
            int i = tid + u * 256;
            if (i < B4) {
                int kk = i / (BN / 4), n4 = i % (BN / 4);
                *(float4*)&Bs[buf][kk][n4 * 4] = rb[u];
            }
        }
    };

    float acc[TM][TN];
#pragma unroll
    for (int i = 0; i < TM; i++)
#pragma unroll
        for (int j = 0; j < TN; j++) acc[i][j] = 0.f;

    loadA(0); loadB(0);
    stageA(0); stageB(0);
    __syncthreads();

    for (int t = 0; t < NT; t++) {
        int buf = t & 1;
        if (t + 1 < NT) { loadA(t + 1); loadB(t + 1); }

#pragma unroll
        for (int k = 0; k < BK; k++) {
            float a[TM], b[TN];
#pragma unroll
            for (int i = 0; i < TM; i += 4) {
                float4 v = *(const float4*)&As[buf][k][ty * TM + i];
                a[i] = v.x; a[i+1] = v.y; a[i+2] = v.z; a[i+3] = v.w;
            }
#pragma unroll
            for (int j = 0; j < TN; j += 4) {
                float4 v = *(const float4*)&Bs[buf][k][tx * TN + j];
                b[j] = v.x; b[j+1] = v.y; b[j+2] = v.z; b[j+3] = v.w;
            }
#pragma unroll
            for (int i = 0; i < TM; i++)
#pragma unroll
                for (int j = 0; j < TN; j++)
                    acc[i][j] = fmaf(a[i], b[j], acc[i][j]);
        }

        if (t + 1 < NT) {
            stageA(buf ^ 1); stageB(buf ^ 1);
            __syncthreads();
        }
    }

#pragma unroll
    for (int i = 0; i < TM; i++) {
        int gr = m0 + ty * TM + i;
        if (gr < M) {
            if (HOUT) {
                __half* C = (__half*)Cv;
#pragma unroll
                for (int j = 0; j < TN; j += 4) {
                    __half2 h0 = __floats2half2_rn(acc[i][j],     acc[i][j + 1]);
                    __half2 h1 = __floats2half2_rn(acc[i][j + 2], acc[i][j + 3]);
                    *(__half2*)&C[(size_t)gr * N + n0 + tx * TN + j]     = h0;
                    *(__half2*)&C[(size_t)gr * N + n0 + tx * TN + j + 2] = h1;
                }
            } else {
                float* C = (float*)Cv;
#pragma unroll
                for (int j = 0; j < TN; j += 4) {
                    float4 v = make_float4(acc[i][j], acc[i][j+1], acc[i][j+2], acc[i][j+3]);
                    *(float4*)&C[(size_t)gr * N + n0 + tx * TN + j] = v;
                }
            }
        }
    }
}

// ---------------------------------------------------------------------------
// CSR SpMM, D=256, fp16 gather table: one warp per row; each lane owns 8
// consecutive columns (uint4 = 8 halves per edge). fp32 accumulation from b1;
// stores relu(acc) in fp32.
// ---------------------------------------------------------------------------
__global__ __launch_bounds__(256)
void spmm256h_csr_kernel(const __half* __restrict__ src, float* __restrict__ out, int n) {
    int row  = (blockIdx.x * blockDim.x + threadIdx.x) >> 5;
    int lane = threadIdx.x & 31;
    if (row >= n) return;

    int start = g_rowptr[row];
    int end   = g_rowptr[row + 1];

    float acc[8];
    {
        float4 b0  = ((const float4*)g_b1)[lane * 2];
        float4 b1v = ((const float4*)g_b1)[lane * 2 + 1];
        acc[0] = b0.x;  acc[1] = b0.y;  acc[2] = b0.z;  acc[3] = b0.w;
        acc[4] = b1v.x; acc[5] = b1v.y; acc[6] = b1v.z; acc[7] = b1v.w;
    }

    auto accum = [&](int2 ed) {
        float v = __int_as_float(ed.y);
        uint4 p = __ldg((const uint4*)(src + (size_t)ed.x * 256) + lane);
        const __half2* hp = (const __half2*)&p;
#pragma unroll
        for (int k = 0; k < 4; k++) {
            float2 f = __half22float2(hp[k]);
            acc[2 * k]     = fmaf(v, f.x, acc[2 * k]);
            acc[2 * k + 1] = fmaf(v, f.y, acc[2 * k + 1]);
        }
    };

    int e = start;
    for (; e + 3 < end; e += 4) {
        int2 e0 = __ldcs(&g_edges[e]);
        int2 e1 = __ldcs(&g_edges[e + 1]);
        int2 e2 = __ldcs(&g_edges[e + 2]);
        int2 e3 = __ldcs(&g_edges[e + 3]);
        accum(e0); accum(e1); accum(e2); accum(e3);
    }
    for (; e < end; e++) accum(__ldcs(&g_edges[e]));

#pragma unroll
    for (int k = 0; k < 8; k++) acc[k] = fmaxf(acc[k], 0.f);

    float4* d = (float4*)(out + (size_t)row * 256 + lane * 8);
    __stcs(&d[0], make_float4(acc[0], acc[1], acc[2], acc[3]));
    __stcs(&d[1], make_float4(acc[4], acc[5], acc[6], acc[7]));
}

// ---------------------------------------------------------------------------
// CSR SpMM, D=64, fp16 gather table: one warp per row; each lane owns 2
// consecutive columns (one __half2 per edge). fp32 accumulation from b2.
// ---------------------------------------------------------------------------
__global__ __launch_bounds__(256)
void spmm64h_csr_kernel(const __half* __restrict__ src, float* __restrict__ out, int n) {
    int row  = (blockIdx.x * blockDim.x + threadIdx.x) >> 5;
    int lane = threadIdx.x & 31;
    if (row >= n) return;

    int start = g_rowptr[row];
    int end   = g_rowptr[row + 1];

    float2 acc = ((const float2*)g_b2)[lane];

    auto accum = [&](int2 ed) {
        float v = __int_as_float(ed.y);
        __half2 h = __ldg((const __half2*)(src + (size_t)ed.x * 64) + lane);
        float2 f = __half22float2(h);
        acc.x = fmaf(v, f.x, acc.x);
        acc.y = fmaf(v, f.y, acc.y);
    };

    int e = start;
    for (; e + 3 < end; e += 4) {
        int2 e0 = __ldcs(&g_edges[e]);
        int2 e1 = __ldcs(&g_edges[e + 1]);
        int2 e2 = __ldcs(&g_edges[e + 2]);
        int2 e3 = __ldcs(&g_edges[e + 3]);
        accum(e0); accum(e1); accum(e2); accum(e3);
    }
    for (; e < end; e++) accum(__ldcs(&g_edges[e]));

    __stcs((float2*)(out + (size_t)row * 64) + lane, acc);
}

// ---------------------------------------------------------------------------
// Launch: CSR build (side stream) runs concurrently with prep+GEMM1 (main).
// ---------------------------------------------------------------------------
extern "C" void kernel_launch(void* const* d_in, const int* in_sizes, int n_in,
                              void* d_out, int out_size) {
    const float* x        = (const float*)d_in[0];
    const int*   edge_row = (const int*)  d_in[1];
    const int*   edge_col = (const int*)  d_in[2];
    const float* edge_val = (const float*)d_in[3];
    const float* w1       = (const float*)d_in[4];
    const float* w2       = (const float*)d_in[5];
    const float* gamma1   = (const float*)d_in[6];
    const float* beta1    = (const float*)d_in[7];
    const float* mean1    = (const float*)d_in[8];
    const float* var1     = (const float*)d_in[9];
    const float* gamma2   = (const float*)d_in[10];
    const float* beta2    = (const float*)d_in[11];
    const float* mean2    = (const float*)d_in[12];
    const float* var2     = (const float*)d_in[13];
    float* out = (float*)d_out;

    const int M = NN;
    const int E = in_sizes[1];

    static __half *p_xw1h = nullptr, *p_hw2h = nullptr;
    static float *p_h = nullptr, *p_w1s = nullptr, *p_w2s = nullptr;
    static int *p_cnt = nullptr;
    static cudaStream_t s_side = nullptr;
    static cudaEvent_t ev_fork = nullptr, ev_join = nullptr;
    if (!p_h) {
        cudaGetSymbolAddress((void**)&p_xw1h, g_xw1h);
        cudaGetSymbolAddress((void**)&p_h,    g_h);
        cudaGetSymbolAddress((void**)&p_hw2h, g_hw2h);
        cudaGetSymbolAddress((void**)&p_w1s,  g_w1s);
        cudaGetSymbolAddress((void**)&p_w2s,  g_w2s);
        cudaGetSymbolAddress((void**)&p_cnt,  g_cnt);
        cudaStreamCreateWithFlags(&s_side, cudaStreamNonBlocking);
        cudaEventCreateWithFlags(&ev_fork, cudaEventDisableTiming);
        cudaEventCreateWithFlags(&ev_join, cudaEventDisableTiming);
    }

    // --- fork: CSR build on side stream ---
    cudaEventRecord(ev_fork, 0);
    cudaStreamWaitEvent(s_side, ev_fork, 0);
    cudaMemsetAsync(p_cnt, 0, NN * sizeof(int), s_side);
    hist_kernel<<<(E + 255) / 256, 256, 0, s_side>>>(edge_row, E);
    scan1_kernel<<<NB_SCAN, 1024, 0, s_side>>>(M);
    scan2_kernel<<<1, 128, 0, s_side>>>(NB_SCAN);
    scan3_kernel<<<(M + 255) / 256, 256, 0, s_side>>>(M, E);
    scatter_kernel<<<(E + 255) / 256, 256, 0, s_side>>>(edge_row, edge_col, edge_val, E);
    cudaEventRecord(ev_join, s_side);

    // --- main stream: prep + GEMM1 (independent of CSR) ---
    prep_kernel<<<IN_DIM, 256>>>(w1, w2, gamma1, beta1, mean1, var1,
                                 gamma2, beta2, mean2, var2);
    {
        dim3 grid((M + 127) / 128, HID / 128);
        sgemm_db_kernel<128, 128, 8, 8, 8, false, true><<<grid, 256>>>(
            x, p_w1s, p_xw1h, M, IN_DIM, HID);
    }

    // --- join, then the dependent chain ---
    cudaStreamWaitEvent(0, ev_join, 0);
    spmm256h_csr_kernel<<<(M * 32 + 255) / 256, 256>>>(p_xw1h, p_h, M);
    {
        dim3 grid((M + 127) / 128, 1);
        sgemm_db_kernel<128, 64, 8, 8, 4, true, true><<<grid, 256>>>(
            p_h, p_w2s, p_hw2h, M, HID, EMB);
    }
    spmm64h_csr_kernel<<<(M * 32 + 255) / 256, 256>>>(p_hw2h, out, M);
}

// round 9
// speedup vs baseline: 4.1539x; 1.8030x over previous
#include <cuda_runtime.h>
#include <cuda_fp16.h>
#include <cstdint>

// Problem constants (fixed by the reference)
#define NN      100000
#define IN_DIM  256
#define HID     256
#define EMB     64
#define E_MAX   3200000
#define BN_EPS  1e-3f
#define NB_SCAN ((NN + 1023) / 1024)   // 98

// ---------------------------------------------------------------------------
// Scratch (device globals: no runtime allocation allowed)
// ---------------------------------------------------------------------------
__device__ __half g_xw1h[(size_t)NN * HID];   // x @ w1'  fp16 (51.2 MB, L2-resident)
__device__ __half g_hh  [(size_t)NN * HID];   // relu(BN1 out) fp16 (51.2 MB)
__device__ __half g_hw2h[(size_t)NN * EMB];   // h @ w2'  fp16 (12.8 MB)
__device__ __half g_w1shT[HID * IN_DIM];      // (w1*s1)^T fp16, [N][K]
__device__ __half g_w2shT[EMB * HID];         // (w2*s2)^T fp16, [N][K]
__device__ float  g_b1[HID];
__device__ float  g_b2[EMB];

// CSR build scratch
__device__ int  g_cnt[NN];
__device__ int  g_excl[NN];
__device__ int  g_bsum[128];
__device__ int  g_bsum2[128];
__device__ int  g_rowptr[NN + 1];
__device__ int  g_roff[NN];
__device__ int2 g_edges[E_MAX];     // (col, val_bits) sorted by row

// ---------------------------------------------------------------------------
// Prep: fold BN scale into weight columns; store transposed fp16 weights.
// grid = IN_DIM blocks, 256 threads.
// ---------------------------------------------------------------------------
__global__ void prep_kernel(const float* __restrict__ w1, const float* __restrict__ w2,
                            const float* __restrict__ g1, const float* __restrict__ be1,
                            const float* __restrict__ m1, const float* __restrict__ v1,
                            const float* __restrict__ g2, const float* __restrict__ be2,
                            const float* __restrict__ m2, const float* __restrict__ v2) {
    int i = blockIdx.x;    // k index (row of w1)
    int j = threadIdx.x;   // n index (col of w1)
    float s1 = g1[j] * rsqrtf(v1[j] + BN_EPS);
    g_w1shT[j * IN_DIM + i] = __float2half_rn(w1[i * HID + j] * s1);
    if (j < EMB) {
        float s2 = g2[j] * rsqrtf(v2[j] + BN_EPS);
        g_w2shT[j * HID + i] = __float2half_rn(w2[i * EMB + j] * s2);
        if (i == 0) g_b2[j] = be2[j] - m2[j] * s2;
    }
    if (i == 0) g_b1[j] = be1[j] - m1[j] * s1;
}

// ---------------------------------------------------------------------------
// CSR construction
// ---------------------------------------------------------------------------
__global__ void hist_kernel(const int* __restrict__ rows, int E) {
    int i = blockIdx.x * blockDim.x + threadIdx.x;
    if (i < E) atomicAdd(&g_cnt[rows[i]], 1);
}

__global__ __launch_bounds__(1024) void scan1_kernel(int n) {
    __shared__ int sh[1024];
    int gid = blockIdx.x * 1024 + threadIdx.x;
    int v = (gid < n) ? g_cnt[gid] : 0;
    sh[threadIdx.x] = v;
    __syncthreads();
#pragma unroll
    for (int off = 1; off < 1024; off <<= 1) {
        int t = (threadIdx.x >= off) ? sh[threadIdx.x - off] : 0;
        __syncthreads();
        sh[threadIdx.x] += t;
        __syncthreads();
    }
    if (gid < n) g_excl[gid] = sh[threadIdx.x] - v;
    if (threadIdx.x == 1023) g_bsum[blockIdx.x] = sh[1023];
}

__global__ void scan2_kernel(int nb) {
    __shared__ int sh[128];
    int t = threadIdx.x;
    int v = (t < nb) ? g_bsum[t] : 0;
    sh[t] = v;
    __syncthreads();
#pragma unroll
    for (int off = 1; off < 128; off <<= 1) {
        int u = (t >= off) ? sh[t - off] : 0;
        __syncthreads();
        sh[t] += u;
        __syncthreads();
    }
    if (t < nb) g_bsum2[t] = sh[t] - v;   // exclusive
}

__global__ void scan3_kernel(int n, int E) {
    int gid = blockIdx.x * blockDim.x + threadIdx.x;
    if (gid < n) {
        int p = g_excl[gid] + g_bsum2[gid >> 10];
        g_rowptr[gid] = p;
        g_roff[gid] = p;
    }
    if (gid == 0) g_rowptr[n] = E;
}

__global__ void scatter_kernel(const int* __restrict__ rows, const int* __restrict__ cols,
                               const float* __restrict__ vals, int E) {
    int i = blockIdx.x * blockDim.x + threadIdx.x;
    if (i < E) {
        int r = rows[i];
        int p = atomicAdd(&g_roff[r], 1);
        g_edges[p] = make_int2(cols[i], __float_as_int(vals[i]));
    }
}

// ---------------------------------------------------------------------------
// fp16 tensor-core GEMM: C[M,N](fp16) = A[M,K] @ BT[N,K]^T, fp32 accumulate.
// BM=128, BK=32, 256 threads (8 warps: 2 m-rows x 4 n-cols).
// AHALF: A is fp16 (loaded streaming); else fp32 converted on load.
// Smem rows padded to 40 halves -> conflict-free fragment loads.
// ---------------------------------------------------------------------------
#define SMP 40   // padded k-stride in halves

template<int BN, int WN, bool AHALF>
__global__ __launch_bounds__(256)
void hgemm_mma_kernel(const void* __restrict__ Av, const __half* __restrict__ BT,
                      __half* __restrict__ C, int M, int K, int N) {
    constexpr int NFRAG = WN / 8;
    __shared__ __half As[2][128 * SMP];
    __shared__ __half Bs[2][BN * SMP];

    const int tid    = threadIdx.x;
    const int lane   = tid & 31;
    const int wid    = tid >> 5;
    const int warp_m = wid >> 2;          // 0..1
    const int warp_n = wid & 3;           // 0..3
    const int tg     = lane & 3;          // thread-in-group
    const int grp    = lane >> 2;         // group id (0..7)
    const int m0     = blockIdx.x * 128;
    const int n0     = blockIdx.y * BN;
    const int NT     = K / 32;

    // staging registers
    float4 raf[4];          // AHALF=false: 4 x float4 (16 floats)
    uint4  rah[2];          // AHALF=true : 2 x uint4  (16 halves)
    uint4  rbv[(BN * 4 + 255) / 256];   // B: BN rows x 4 uint4 per row

    auto loadA = [&](int t) {
        if (AHALF) {
            const __half* A = (const __half*)Av;
#pragma unroll
            for (int u = 0; u < 2; u++) {
                int idx = tid + u * 256;          // 512 uint4 total
                int row = idx >> 2, q = idx & 3;  // 4 uint4 per row
                int gr = m0 + row;
                rah[u] = (gr < M)
                    ? __ldcs((const uint4*)(A + (size_t)gr * K + t * 32 + q * 8))
                    : make_uint4(0, 0, 0, 0);
            }
        } else {
            const float* A = (const float*)Av;
#pragma unroll
            for (int u = 0; u < 4; u++) {
                int idx = tid + u * 256;          // 1024 float4 total
                int row = idx >> 3, c4 = idx & 7; // 8 float4 per row
                int gr = m0 + row;
                raf[u] = (gr < M)
                    ? __ldcs((const float4*)(A + (size_t)gr * K + t * 32 + c4 * 4))
                    : make_float4(0.f, 0.f, 0.f, 0.f);
            }
        }
    };
    auto stageA = [&](int buf) {
        if (AHALF) {
#pragma unroll
            for (int u = 0; u < 2; u++) {
                int idx = tid + u * 256;
                int row = idx >> 2, q = idx & 3;
                uint2* p = (uint2*)&As[buf][row * SMP + q * 8];
                p[0] = make_uint2(rah[u].x, rah[u].y);
                p[1] = make_uint2(rah[u].z, rah[u].w);
            }
        } else {
#pragma unroll
            for (int u = 0; u < 4; u++) {
                int idx = tid + u * 256;
                int row = idx >> 3, c4 = idx & 7;
                __half2 h0 = __floats2half2_rn(raf[u].x, raf[u].y);
                __half2 h1 = __floats2half2_rn(raf[u].z, raf[u].w);
                *(uint2*)&As[buf][row * SMP + c4 * 4] =
                    make_uint2(*(unsigned*)&h0, *(unsigned*)&h1);
            }
        }
    };
    auto loadB = [&](int t) {
        constexpr int NB4 = BN * 4;
#pragma unroll
        for (int u = 0; u < (NB4 + 255) / 256; u++) {
            int idx = tid + u * 256;
            if (idx < NB4) {
                int row = idx >> 2, q = idx & 3;
                rbv[u] = __ldg((const uint4*)(BT + (size_t)(n0 + row) * K + t * 32 + q * 8));
            }
        }
    };
    auto stageB = [&](int buf) {
        constexpr int NB4 = BN * 4;
#pragma unroll
        for (int u = 0; u < (NB4 + 255) / 256; u++) {
            int idx = tid + u * 256;
            if (idx < NB4) {
                int row = idx >> 2, q = idx & 3;
                uint2* p = (uint2*)&Bs[buf][row * SMP + q * 8];
                p[0] = make_uint2(rbv[u].x, rbv[u].y);
                p[1] = make_uint2(rbv[u].z, rbv[u].w);
            }
        }
    };

    float acc[4][NFRAG][4];
#pragma unroll
    for (int i = 0; i < 4; i++)
#pragma unroll
        for (int j = 0; j < NFRAG; j++)
#pragma unroll
            for (int c = 0; c < 4; c++) acc[i][j][c] = 0.f;

    loadA(0); loadB(0);
    stageA(0); stageB(0);
    __syncthreads();

    for (int t = 0; t < NT; t++) {
        int buf = t & 1;
        if (t + 1 < NT) { loadA(t + 1); loadB(t + 1); }

#pragma unroll
        for (int ks = 0; ks < 32; ks += 16) {
            unsigned a[4][4];
#pragma unroll
            for (int mf = 0; mf < 4; mf++) {
                int r = warp_m * 64 + mf * 16 + grp;
                int kc = ks + tg * 2;
                a[mf][0] = *(const unsigned*)&As[buf][r * SMP + kc];
                a[mf][1] = *(const unsigned*)&As[buf][(r + 8) * SMP + kc];
                a[mf][2] = *(const unsigned*)&As[buf][r * SMP + kc + 8];
                a[mf][3] = *(const unsigned*)&As[buf][(r + 8) * SMP + kc + 8];
            }
            unsigned b[NFRAG][2];
#pragma unroll
            for (int nf = 0; nf < NFRAG; nf++) {
                int n = warp_n * WN + nf * 8 + grp;
                int kc = ks + tg * 2;
                b[nf][0] = *(const unsigned*)&Bs[buf][n * SMP + kc];
                b[nf][1] = *(const unsigned*)&Bs[buf][n * SMP + kc + 8];
            }
#pragma unroll
            for (int mf = 0; mf < 4; mf++)
#pragma unroll
                for (int nf = 0; nf < NFRAG; nf++) {
                    asm volatile(
                        "mma.sync.aligned.m16n8k16.row.col.f32.f16.f16.f32 "
                        "{%0,%1,%2,%3}, {%4,%5,%6,%7}, {%8,%9}, {%0,%1,%2,%3};"
                        : "+f"(acc[mf][nf][0]), "+f"(acc[mf][nf][1]),
                          "+f"(acc[mf][nf][2]), "+f"(acc[mf][nf][3])
                        : "r"(a[mf][0]), "r"(a[mf][1]), "r"(a[mf][2]), "r"(a[mf][3]),
                          "r"(b[nf][0]), "r"(b[nf][1]));
                }
        }

        if (t + 1 < NT) {
            stageA(buf ^ 1); stageB(buf ^ 1);
            __syncthreads();
        }
    }

    // Epilogue: fp16 stores
#pragma unroll
    for (int mf = 0; mf < 4; mf++) {
        int row0 = m0 + warp_m * 64 + mf * 16 + grp;
#pragma unroll
        for (int nf = 0; nf < NFRAG; nf++) {
            int col = n0 + warp_n * WN + nf * 8 + tg * 2;
            if (row0 < M) {
                __half2 h = __floats2half2_rn(acc[mf][nf][0], acc[mf][nf][1]);
                *(__half2*)&C[(size_t)row0 * N + col] = h;
            }
            if (row0 + 8 < M) {
                __half2 h = __floats2half2_rn(acc[mf][nf][2], acc[mf][nf][3]);
                *(__half2*)&C[(size_t)(row0 + 8) * N + col] = h;
            }
        }
    }
}

// ---------------------------------------------------------------------------
// CSR SpMM, D=256, fp16 gather table: one warp per row; each lane owns 8
// consecutive columns (uint4 = 8 halves per edge). fp32 accumulation from b1;
// stores relu(acc) as fp16 (uint4 per lane).
// ---------------------------------------------------------------------------
__global__ __launch_bounds__(256)
void spmm256h_csr_kernel(const __half* __restrict__ src, __half* __restrict__ out, int n) {
    int row  = (blockIdx.x * blockDim.x + threadIdx.x) >> 5;
    int lane = threadIdx.x & 31;
    if (row >= n) return;

    int start = g_rowptr[row];
    int end   = g_rowptr[row + 1];

    float acc[8];
    {
        float4 b0  = ((const float4*)g_b1)[lane * 2];
        float4 b1v = ((const float4*)g_b1)[lane * 2 + 1];
        acc[0] = b0.x;  acc[1] = b0.y;  acc[2] = b0.z;  acc[3] = b0.w;
        acc[4] = b1v.x; acc[5] = b1v.y; acc[6] = b1v.z; acc[7] = b1v.w;
    }

    auto accum = [&](int2 ed) {
        float v = __int_as_float(ed.y);
        uint4 p = __ldg((const uint4*)(src + (size_t)ed.x * 256) + lane);
        const __half2* hp = (const __half2*)&p;
#pragma unroll
        for (int k = 0; k < 4; k++) {
            float2 f = __half22float2(hp[k]);
            acc[2 * k]     = fmaf(v, f.x, acc[2 * k]);
            acc[2 * k + 1] = fmaf(v, f.y, acc[2 * k + 1]);
        }
    };

    int e = start;
    for (; e + 3 < end; e += 4) {
        int2 e0 = __ldcs(&g_edges[e]);
        int2 e1 = __ldcs(&g_edges[e + 1]);
        int2 e2 = __ldcs(&g_edges[e + 2]);
        int2 e3 = __ldcs(&g_edges[e + 3]);
        accum(e0); accum(e1); accum(e2); accum(e3);
    }
    for (; e < end; e++) accum(__ldcs(&g_edges[e]));

    __half2 h0 = __floats2half2_rn(fmaxf(acc[0], 0.f), fmaxf(acc[1], 0.f));
    __half2 h1 = __floats2half2_rn(fmaxf(acc[2], 0.f), fmaxf(acc[3], 0.f));
    __half2 h2 = __floats2half2_rn(fmaxf(acc[4], 0.f), fmaxf(acc[5], 0.f));
    __half2 h3 = __floats2half2_rn(fmaxf(acc[6], 0.f), fmaxf(acc[7], 0.f));
    uint4 pk = make_uint4(*(unsigned*)&h0, *(unsigned*)&h1,
                          *(unsigned*)&h2, *(unsigned*)&h3);
    __stcs((uint4*)(out + (size_t)row * 256 + lane * 8), pk);
}

// ---------------------------------------------------------------------------
// CSR SpMM, D=64, fp16 gather table: one warp per row; each lane owns 2
// consecutive columns. fp32 accumulation from b2; fp32 output (final answer).
// ---------------------------------------------------------------------------
__global__ __launch_bounds__(256)
void spmm64h_csr_kernel(const __half* __restrict__ src, float* __restrict__ out, int n) {
    int row  = (blockIdx.x * blockDim.x + threadIdx.x) >> 5;
    int lane = threadIdx.x & 31;
    if (row >= n) return;

    int start = g_rowptr[row];
    int end   = g_rowptr[row + 1];

    float2 acc = ((const float2*)g_b2)[lane];

    auto accum = [&](int2 ed) {
        float v = __int_as_float(ed.y);
        __half2 h = __ldg((const __half2*)(src + (size_t)ed.x * 64) + lane);
        float2 f = __half22float2(h);
        acc.x = fmaf(v, f.x, acc.x);
        acc.y = fmaf(v, f.y, acc.y);
    };

    int e = start;
    for (; e + 3 < end; e += 4) {
        int2 e0 = __ldcs(&g_edges[e]);
        int2 e1 = __ldcs(&g_edges[e + 1]);
        int2 e2 = __ldcs(&g_edges[e + 2]);
        int2 e3 = __ldcs(&g_edges[e + 3]);
        accum(e0); accum(e1); accum(e2); accum(e3);
    }
    for (; e < end; e++) accum(__ldcs(&g_edges[e]));

    __stcs((float2*)(out + (size_t)row * 64) + lane, acc);
}

// ---------------------------------------------------------------------------
// Launch: CSR build (side stream) runs concurrently with prep+GEMM1 (main).
// ---------------------------------------------------------------------------
extern "C" void kernel_launch(void* const* d_in, const int* in_sizes, int n_in,
                              void* d_out, int out_size) {
    const float* x        = (const float*)d_in[0];
    const int*   edge_row = (const int*)  d_in[1];
    const int*   edge_col = (const int*)  d_in[2];
    const float* edge_val = (const float*)d_in[3];
    const float* w1       = (const float*)d_in[4];
    const float* w2       = (const float*)d_in[5];
    const float* gamma1   = (const float*)d_in[6];
    const float* beta1    = (const float*)d_in[7];
    const float* mean1    = (const float*)d_in[8];
    const float* var1     = (const float*)d_in[9];
    const float* gamma2   = (const float*)d_in[10];
    const float* beta2    = (const float*)d_in[11];
    const float* mean2    = (const float*)d_in[12];
    const float* var2     = (const float*)d_in[13];
    float* out = (float*)d_out;

    const int M = NN;
    const int E = in_sizes[1];

    static __half *p_xw1h = nullptr, *p_hh = nullptr, *p_hw2h = nullptr,
                  *p_w1shT = nullptr, *p_w2shT = nullptr;
    static int *p_cnt = nullptr;
    static cudaStream_t s_side = nullptr;
    static cudaEvent_t ev_fork = nullptr, ev_join = nullptr;
    if (!p_xw1h) {
        cudaGetSymbolAddress((void**)&p_xw1h,  g_xw1h);
        cudaGetSymbolAddress((void**)&p_hh,    g_hh);
        cudaGetSymbolAddress((void**)&p_hw2h,  g_hw2h);
        cudaGetSymbolAddress((void**)&p_w1shT, g_w1shT);
        cudaGetSymbolAddress((void**)&p_w2shT, g_w2shT);
        cudaGetSymbolAddress((void**)&p_cnt,   g_cnt);
        cudaStreamCreateWithFlags(&s_side, cudaStreamNonBlocking);
        cudaEventCreateWithFlags(&ev_fork, cudaEventDisableTiming);
        cudaEventCreateWithFlags(&ev_join, cudaEventDisableTiming);
    }

    // --- fork: CSR build on side stream ---
    cudaEventRecord(ev_fork, 0);
    cudaStreamWaitEvent(s_side, ev_fork, 0);
    cudaMemsetAsync(p_cnt, 0, NN * sizeof(int), s_side);
    hist_kernel<<<(E + 255) / 256, 256, 0, s_side>>>(edge_row, E);
    scan1_kernel<<<NB_SCAN, 1024, 0, s_side>>>(M);
    scan2_kernel<<<1, 128, 0, s_side>>>(NB_SCAN);
    scan3_kernel<<<(M + 255) / 256, 256, 0, s_side>>>(M, E);
    scatter_kernel<<<(E + 255) / 256, 256, 0, s_side>>>(edge_row, edge_col, edge_val, E);
    cudaEventRecord(ev_join, s_side);

    // --- main stream: prep + GEMM1 (tensor core) ---
    prep_kernel<<<IN_DIM, 256>>>(w1, w2, gamma1, beta1, mean1, var1,
                                 gamma2, beta2, mean2, var2);
    {
        dim3 grid((M + 127) / 128, HID / 128);   // 782 x 2
        hgemm_mma_kernel<128, 32, false><<<grid, 256>>>(
            x, p_w1shT, p_xw1h, M, IN_DIM, HID);
    }

    // --- join, then the dependent chain ---
    cudaStreamWaitEvent(0, ev_join, 0);
    spmm256h_csr_kernel<<<(M * 32 + 255) / 256, 256>>>(p_xw1h, p_hh, M);
    {
        dim3 grid((M + 127) / 128, 1);           // 782 x 1
        hgemm_mma_kernel<64, 16, true><<<grid, 256>>>(
            p_hh, p_w2shT, p_hw2h, M, HID, EMB);
    }
    spmm64h_csr_kernel<<<(M * 32 + 255) / 256, 256>>>(p_hw2h, out, M);
}